// round 1
// baseline (speedup 1.0000x reference)
#include <cuda_runtime.h>
#include <math.h>

// ---------------- problem constants ----------------
#define BB 8
#define NN 5000
#define EE 80000
#define IND 30
#define HH 4
#define DD 64
#define HD 256
#define OUTD 3
#define TSTEPS 5
#define EPSBN 1e-5f
#define MROWS (BB*NN)   // 40000

// ---------------- device scratch (no allocations allowed) ----------------
__device__ float g_x[MROWS * IND];        // working xx
__device__ float g_h[MROWS * HD];         // fc output (pre-aggregation)
__device__ float g_hout[MROWS * HD];      // aggregated / normalized output
__device__ float g_el[MROWS * HH];
__device__ float g_er[MROWS * HH];
__device__ int   g_deg[NN];
__device__ int   g_off[NN];
__device__ int   g_rowstart[NN + 1];
__device__ int   g_csr_src[EE];
__device__ float g_sum[HD];
__device__ float g_sumsq[HD];
__device__ float g_scale[HD];
__device__ float g_shift[HD];

__device__ __forceinline__ float lk(float x, float s) { return x > 0.f ? x : s * x; }

// ---------------- init / CSR build ----------------
__global__ void k_copyx(const float* __restrict__ xx) {
    int i = blockIdx.x * blockDim.x + threadIdx.x;
    if (i < MROWS * IND) g_x[i] = xx[i];
}

__global__ void k_zero_counts() {
    int i = blockIdx.x * blockDim.x + threadIdx.x;
    if (i < NN) { g_deg[i] = 0; g_off[i] = 0; }
}

__global__ void k_count(const int* __restrict__ dst) {
    int e = blockIdx.x * blockDim.x + threadIdx.x;
    if (e < EE) atomicAdd(&g_deg[dst[e]], 1);
}

__global__ void k_scan() {  // single block, 1024 threads, chunked Hillis-Steele
    __shared__ int sh[1024];
    int t = threadIdx.x;
    int carry = 0;
    for (int base = 0; base < NN; base += 1024) {
        int v = (base + t < NN) ? g_deg[base + t] : 0;
        sh[t] = v;
        __syncthreads();
        for (int off = 1; off < 1024; off <<= 1) {
            int x = (t >= off) ? sh[t - off] : 0;
            __syncthreads();
            sh[t] += x;
            __syncthreads();
        }
        if (base + t < NN) g_rowstart[base + t] = carry + sh[t] - v;
        int tot = sh[1023];
        __syncthreads();
        carry += tot;
    }
    if (t == 0) g_rowstart[NN] = carry;
}

__global__ void k_fill(const int* __restrict__ src, const int* __restrict__ dst) {
    int e = blockIdx.x * blockDim.x + threadIdx.x;
    if (e < EE) {
        int v = dst[e];
        int p = atomicAdd(&g_off[v], 1);
        g_csr_src[g_rowstart[v] + p] = src[e];
    }
}

// ---------------- layer-0 FC (K=30) ----------------
__global__ void k_fc0(const float* __restrict__ W) {
    __shared__ float sx[IND];
    int m = blockIdx.x;
    int t = threadIdx.x;
    if (t < IND) sx[t] = g_x[m * IND + t];
    __syncthreads();
    float acc = 0.f;
#pragma unroll
    for (int k = 0; k < IND; k++) acc += sx[k] * W[k * HD + t];
    g_h[m * HD + t] = acc;
}

// ---------------- main SGEMM: g_h = g_hout[M,256] @ W[256,256] ----------------
#define BM 128
#define BNT 128
#define BK 8
__global__ __launch_bounds__(256) void k_sgemm(const float* __restrict__ Wm) {
    __shared__ float As[BK][BM];
    __shared__ float Bs[BK][BNT];
    const int tid = threadIdx.x;
    const int bx = blockIdx.x;          // 0..1 over N'=256
    const int by = blockIdx.y;          // over M
    const int tx = tid & 15, ty = tid >> 4;
    const int row0 = by * BM;

    const int a_r = tid >> 1, a_c = (tid & 1) << 2;   // A tile loader
    const int b_r = tid >> 5, b_c = (tid & 31) << 2;  // B tile loader

    float acc[8][8];
#pragma unroll
    for (int i = 0; i < 8; i++)
#pragma unroll
        for (int j = 0; j < 8; j++) acc[i][j] = 0.f;

    for (int k0 = 0; k0 < HD; k0 += BK) {
        float4 av = make_float4(0.f, 0.f, 0.f, 0.f);
        int gr = row0 + a_r;
        if (gr < MROWS) av = *(const float4*)&g_hout[gr * HD + k0 + a_c];
        As[a_c + 0][a_r] = av.x;
        As[a_c + 1][a_r] = av.y;
        As[a_c + 2][a_r] = av.z;
        As[a_c + 3][a_r] = av.w;
        float4 bv = *(const float4*)&Wm[(k0 + b_r) * HD + bx * BNT + b_c];
        *(float4*)&Bs[b_r][b_c] = bv;
        __syncthreads();
#pragma unroll
        for (int k = 0; k < BK; k++) {
            float ar[8], br[8];
            float4 a0 = *(const float4*)&As[k][ty * 8];
            float4 a1 = *(const float4*)&As[k][ty * 8 + 4];
            ar[0]=a0.x; ar[1]=a0.y; ar[2]=a0.z; ar[3]=a0.w;
            ar[4]=a1.x; ar[5]=a1.y; ar[6]=a1.z; ar[7]=a1.w;
            float4 b0 = *(const float4*)&Bs[k][tx * 8];
            float4 b1 = *(const float4*)&Bs[k][tx * 8 + 4];
            br[0]=b0.x; br[1]=b0.y; br[2]=b0.z; br[3]=b0.w;
            br[4]=b1.x; br[5]=b1.y; br[6]=b1.z; br[7]=b1.w;
#pragma unroll
            for (int i = 0; i < 8; i++)
#pragma unroll
                for (int j = 0; j < 8; j++) acc[i][j] += ar[i] * br[j];
        }
        __syncthreads();
    }
    const int col0 = bx * BNT + tx * 8;
#pragma unroll
    for (int i = 0; i < 8; i++) {
        int gr = row0 + ty * 8 + i;
        if (gr < MROWS) {
            float4 v0 = make_float4(acc[i][0], acc[i][1], acc[i][2], acc[i][3]);
            float4 v1 = make_float4(acc[i][4], acc[i][5], acc[i][6], acc[i][7]);
            *(float4*)&g_h[gr * HD + col0] = v0;
            *(float4*)&g_h[gr * HD + col0 + 4] = v1;
        }
    }
}

// ---------------- per-node attention logits el/er ----------------
__global__ void k_eler(const float* __restrict__ al, const float* __restrict__ ar) {
    int m = blockIdx.x;                  // b*N+n
    int w = threadIdx.x >> 5, lane = threadIdx.x & 31;
    const float* hp = g_h + m * HD + w * DD;
    float a0 = hp[lane], a1 = hp[lane + 32];
    float el = a0 * al[w * DD + lane] + a1 * al[w * DD + lane + 32];
    float er = a0 * ar[w * DD + lane] + a1 * ar[w * DD + lane + 32];
#pragma unroll
    for (int off = 16; off; off >>= 1) {
        el += __shfl_xor_sync(0xffffffffu, el, off);
        er += __shfl_xor_sync(0xffffffffu, er, off);
    }
    if (lane == 0) {
        g_el[m * HH + w] = el;
        g_er[m * HH + w] = er;
    }
}

// ---------------- edge softmax + aggregation (CSR, atomic-free) ----------------
__global__ __launch_bounds__(256) void k_agg() {
    const int bn = blockIdx.x;          // b*N + v
    const int b  = bn / NN;
    const int v  = bn - b * NN;
    const int t  = threadIdx.x;
    const int hh = t >> 6;              // head for accumulation
    const int d  = t & 63;

    const int e0 = g_rowstart[v];
    const int deg = g_rowstart[v + 1] - e0;
    float* outp = g_hout + bn * HD;
    if (deg == 0) { outp[t] = 0.f; return; }

    __shared__ float sh_er[HH];
    __shared__ float sh_m[HH];
    __shared__ float sh_is[HH];
    __shared__ float sh_w[HH][32];
    __shared__ int   sh_src[32];

    if (t < HH) sh_er[t] = g_er[bn * HH + t];
    __syncthreads();

    const int w = t >> 5, lane = t & 31;
    // pass A: per-head max (warps 0..3)
    if (w < HH) {
        float mv = -INFINITY;
        for (int i = lane; i < deg; i += 32) {
            int s = g_csr_src[e0 + i];
            float e = lk(g_el[(b * NN + s) * HH + w] + sh_er[w], 0.2f);
            mv = fmaxf(mv, e);
        }
#pragma unroll
        for (int off = 16; off; off >>= 1) mv = fmaxf(mv, __shfl_xor_sync(0xffffffffu, mv, off));
        if (lane == 0) sh_m[w] = mv;
    }
    __syncthreads();
    // pass B: per-head sum of exp
    if (w < HH) {
        float sum = 0.f;
        float m = sh_m[w];
        for (int i = lane; i < deg; i += 32) {
            int s = g_csr_src[e0 + i];
            float e = lk(g_el[(b * NN + s) * HH + w] + sh_er[w], 0.2f);
            sum += __expf(e - m);
        }
#pragma unroll
        for (int off = 16; off; off >>= 1) sum += __shfl_xor_sync(0xffffffffu, sum, off);
        if (lane == 0) sh_is[w] = 1.f / sum;
    }
    __syncthreads();
    // pass C: weighted scatter-sum, chunks of 32 edges
    float acc = 0.f;
    for (int base = 0; base < deg; base += 32) {
        int len = min(32, deg - base);
        if (t < 128) {
            int i = t & 31, h2 = t >> 5;
            if (i < len) {
                int s = g_csr_src[e0 + base + i];
                if (t < 32) sh_src[i] = s;
                float e = lk(g_el[(b * NN + s) * HH + h2] + sh_er[h2], 0.2f);
                sh_w[h2][i] = __expf(e - sh_m[h2]) * sh_is[h2];
            }
        }
        __syncthreads();
        for (int i = 0; i < len; i++) {
            int s = sh_src[i];
            acc += sh_w[hh][i] * g_h[((b * NN + s) << 8) + (hh << 6) + d];
        }
        __syncthreads();
    }
    outp[t] = acc;
}

// ---------------- BatchNorm ----------------
__global__ void k_bnzero() {
    int t = threadIdx.x;
    if (t < HD) { g_sum[t] = 0.f; g_sumsq[t] = 0.f; }
}

__global__ void k_bnstats() {
    int c = threadIdx.x;
    float s = 0.f, sq = 0.f;
    for (int r = blockIdx.x; r < MROWS; r += gridDim.x) {
        float x = g_hout[r * HD + c];
        s += x;
        sq += x * x;
    }
    atomicAdd(&g_sum[c], s);
    atomicAdd(&g_sumsq[c], sq);
}

__global__ void k_bnfin(const float* __restrict__ gamma, const float* __restrict__ beta) {
    int c = threadIdx.x;
    if (c < HD) {
        float inv = 1.f / (float)MROWS;
        float mu = g_sum[c] * inv;
        float var = g_sumsq[c] * inv - mu * mu;
        float sc = gamma[c] * rsqrtf(var + EPSBN);
        g_scale[c] = sc;
        g_shift[c] = beta[c] - mu * sc;
    }
}

__global__ void k_bnapply() {
    int i = blockIdx.x * blockDim.x + threadIdx.x;
    int total = MROWS * HD / 4;
    if (i >= total) return;
    float4 v = ((float4*)g_hout)[i];
    int c = (i * 4) & (HD - 1);
    v.x = lk(v.x * g_scale[c + 0] + g_shift[c + 0], 0.01f);
    v.y = lk(v.y * g_scale[c + 1] + g_shift[c + 1], 0.01f);
    v.z = lk(v.z * g_scale[c + 2] + g_shift[c + 2], 0.01f);
    v.w = lk(v.w * g_scale[c + 3] + g_shift[c + 3], 0.01f);
    ((float4*)g_hout)[i] = v;
}

// ---------------- output projection + autoregressive shift ----------------
__global__ void k_proj(const float* __restrict__ Wo, const float* __restrict__ bo,
                       float* __restrict__ out, int step) {
    int bn = blockIdx.x;
    int w = threadIdx.x >> 5, lane = threadIdx.x & 31;
    __shared__ float sval[OUTD];
    const float* hp = g_hout + bn * HD;
    float sum = 0.f;
#pragma unroll
    for (int k = lane; k < HD; k += 32) sum += hp[k] * Wo[k * OUTD + w];
#pragma unroll
    for (int off = 16; off; off >>= 1) sum += __shfl_xor_sync(0xffffffffu, sum, off);
    if (lane == 0) sval[w] = sum + bo[w];

    float keep = 0.f;
    if (threadIdx.x < IND - OUTD) keep = g_x[bn * IND + threadIdx.x + OUTD];
    __syncthreads();
    if (threadIdx.x < IND - OUTD) g_x[bn * IND + threadIdx.x] = keep;
    else if (threadIdx.x < IND) g_x[bn * IND + threadIdx.x] = sval[threadIdx.x - (IND - OUTD)];
    if (threadIdx.x < OUTD) out[(bn * TSTEPS + step) * OUTD + threadIdx.x] = sval[threadIdx.x];
}

// ---------------- launcher ----------------
extern "C" void kernel_launch(void* const* d_in, const int* in_sizes, int n_in,
                              void* d_out, int out_size) {
    const float* xx  = (const float*)d_in[0];
    const int*   src = (const int*)d_in[1];
    const int*   dst = (const int*)d_in[2];
    const float *W[4], *al[4], *ar[4], *gamma[4], *beta[4];
    for (int l = 0; l < 4; l++) {
        W[l]     = (const float*)d_in[3 + 5 * l];
        al[l]    = (const float*)d_in[4 + 5 * l];
        ar[l]    = (const float*)d_in[5 + 5 * l];
        gamma[l] = (const float*)d_in[6 + 5 * l];
        beta[l]  = (const float*)d_in[7 + 5 * l];
    }
    const float* W_out = (const float*)d_in[23];
    const float* b_out = (const float*)d_in[24];
    float* out = (float*)d_out;

    // init working xx + CSR (static graph, rebuilt idempotently each call)
    k_copyx<<<(MROWS * IND + 255) / 256, 256>>>(xx);
    k_zero_counts<<<(NN + 255) / 256, 256>>>();
    k_count<<<(EE + 255) / 256, 256>>>(dst);
    k_scan<<<1, 1024>>>();
    k_fill<<<(EE + 255) / 256, 256>>>(src, dst);

    dim3 gemm_grid(HD / BNT, (MROWS + BM - 1) / BM);

    for (int step = 0; step < TSTEPS; step++) {
        for (int l = 0; l < 4; l++) {
            if (l == 0)
                k_fc0<<<MROWS, 256>>>(W[0]);
            else
                k_sgemm<<<gemm_grid, 256>>>(W[l]);
            k_eler<<<MROWS, 128>>>(al[l], ar[l]);
            k_agg<<<MROWS, 256>>>();
            k_bnzero<<<1, 256>>>();
            k_bnstats<<<512, 256>>>();
            k_bnfin<<<1, 256>>>(gamma[l], beta[l]);
            k_bnapply<<<(MROWS * HD / 4 + 255) / 256, 256>>>();
        }
        k_proj<<<MROWS, 96>>>(W_out, b_out, out, step);
    }
}

// round 4
// speedup vs baseline: 1.2663x; 1.2663x over previous
#include <cuda_runtime.h>
#include <cuda_bf16.h>
#include <math.h>
#include <stdint.h>

// ---------------- problem constants ----------------
#define BB 8
#define NN 5000
#define EE 80000
#define IND 30
#define HH 4
#define DD 64
#define HD 256
#define OUTD 3
#define TSTEPS 5
#define EPSBN 1e-5f
#define MROWS (BB*NN)   // 40000

// GEMM tiling
#define TM 128
#define TN 128
#define KC 64           // k chunk
#define ASTR 72         // padded smem stride (bf16 elems) -> 144B, conflict-free ldmatrix
#define NPART 64        // BN partial slots

#define GSM_BYTES (4 * 128 * ASTR * 2)   // Ahi, Alo, Bhi, Blo = 73728

// ---------------- device scratch ----------------
__device__ float g_x[MROWS * IND];
__device__ float g_h[MROWS * HD];
__device__ float g_hout[MROWS * HD];
__device__ float g_el[MROWS * HH];
__device__ float g_er[MROWS * HH];
__device__ int   g_deg[NN];
__device__ int   g_off[NN];
__device__ int   g_rowstart[NN + 1];
__device__ int   g_csr_src[EE];
__device__ float g_part[NPART * HD];
__device__ float g_partsq[NPART * HD];
__device__ float g_scale[HD];
__device__ float g_shift[HD];
__device__ __nv_bfloat16 g_wthi[3 * HD * HD];   // [l][n][k]
__device__ __nv_bfloat16 g_wtlo[3 * HD * HD];

__device__ __forceinline__ float lk(float x, float s) { return x > 0.f ? x : s * x; }

__device__ __forceinline__ uint32_t s2u(const void* p) {
    uint32_t a;
    asm("{ .reg .u64 t; cvta.to.shared.u64 t, %1; cvt.u32.u64 %0, t; }" : "=r"(a) : "l"(p));
    return a;
}
__device__ __forceinline__ void ldsm4(uint32_t* r, uint32_t a) {
    asm volatile("ldmatrix.sync.aligned.m8n8.x4.shared.b16 {%0,%1,%2,%3}, [%4];"
                 : "=r"(r[0]), "=r"(r[1]), "=r"(r[2]), "=r"(r[3]) : "r"(a));
}
__device__ __forceinline__ void mma16816(float* c, const uint32_t* a, const uint32_t* b) {
    asm volatile(
        "mma.sync.aligned.m16n8k16.row.col.f32.bf16.bf16.f32 "
        "{%0,%1,%2,%3}, {%4,%5,%6,%7}, {%8,%9}, {%0,%1,%2,%3};"
        : "+f"(c[0]), "+f"(c[1]), "+f"(c[2]), "+f"(c[3])
        : "r"(a[0]), "r"(a[1]), "r"(a[2]), "r"(a[3]), "r"(b[0]), "r"(b[1]));
}

// ---------------- init / CSR build ----------------
__global__ void k_copyx(const float* __restrict__ xx) {
    int i = blockIdx.x * blockDim.x + threadIdx.x;
    if (i < MROWS * IND) g_x[i] = xx[i];
}
__global__ void k_zero_counts() {
    int i = blockIdx.x * blockDim.x + threadIdx.x;
    if (i < NN) { g_deg[i] = 0; g_off[i] = 0; }
}
__global__ void k_count(const int* __restrict__ dst) {
    int e = blockIdx.x * blockDim.x + threadIdx.x;
    if (e < EE) atomicAdd(&g_deg[dst[e]], 1);
}
__global__ void k_scan() {
    __shared__ int sh[1024];
    int t = threadIdx.x;
    int carry = 0;
    for (int base = 0; base < NN; base += 1024) {
        int v = (base + t < NN) ? g_deg[base + t] : 0;
        sh[t] = v;
        __syncthreads();
        for (int off = 1; off < 1024; off <<= 1) {
            int x = (t >= off) ? sh[t - off] : 0;
            __syncthreads();
            sh[t] += x;
            __syncthreads();
        }
        if (base + t < NN) g_rowstart[base + t] = carry + sh[t] - v;
        int tot = sh[1023];
        __syncthreads();
        carry += tot;
    }
    if (t == 0) g_rowstart[NN] = carry;
}
__global__ void k_fill(const int* __restrict__ src, const int* __restrict__ dst) {
    int e = blockIdx.x * blockDim.x + threadIdx.x;
    if (e < EE) {
        int v = dst[e];
        int p = atomicAdd(&g_off[v], 1);
        g_csr_src[g_rowstart[v] + p] = src[e];
    }
}

// ---------------- W transpose + bf16 split  (W[k][n] -> wt[n][k]) ----------------
__global__ void k_wprep(const float* __restrict__ W1, const float* __restrict__ W2,
                        const float* __restrict__ W3) {
    int k = blockIdx.x;
    int l = blockIdx.y;
    int n = threadIdx.x;
    const float* W = (l == 0) ? W1 : (l == 1) ? W2 : W3;
    float v = W[k * HD + n];
    __nv_bfloat16 h = __float2bfloat16(v);
    float lo = v - __bfloat162float(h);
    int o = l * HD * HD + n * HD + k;
    g_wthi[o] = h;
    g_wtlo[o] = __float2bfloat16(lo);
}

// ---------------- layer-0 FC (K=30) with fused el/er ----------------
__global__ void k_fc0(const float* __restrict__ W, const float* __restrict__ al,
                      const float* __restrict__ ar) {
    __shared__ float sx[IND];
    __shared__ float p_el[8], p_er[8];
    int m = blockIdx.x;
    int t = threadIdx.x;
    if (t < IND) sx[t] = g_x[m * IND + t];
    __syncthreads();
    float acc = 0.f;
#pragma unroll
    for (int k = 0; k < IND; k++) acc += sx[k] * W[k * HD + t];
    g_h[m * HD + t] = acc;

    float ve = acc * al[t];
    float vr = acc * ar[t];
#pragma unroll
    for (int off = 16; off; off >>= 1) {
        ve += __shfl_xor_sync(0xffffffffu, ve, off);
        vr += __shfl_xor_sync(0xffffffffu, vr, off);
    }
    int w = t >> 5, lane = t & 31;
    if (lane == 0) { p_el[w] = ve; p_er[w] = vr; }
    __syncthreads();
    if (t < HH) {
        g_el[m * HH + t] = p_el[2 * t] + p_el[2 * t + 1];
        g_er[m * HH + t] = p_er[2 * t] + p_er[2 * t + 1];
    }
}

// ---------------- HMMA GEMM: g_h = lrelu(BN(g_hout)) @ W, fused el/er ----------------
// grid (2, 313), 256 threads. CTA 128x128, warp 32x64, K=256 in 4 chunks of 64.
// bf16 split-2: D = Ahi*Bhi + Ahi*Blo + Alo*Bhi  (fp32 accumulate in registers)
__global__ __launch_bounds__(256) void k_gemm(int wsel, const float* __restrict__ al,
                                              const float* __restrict__ ar) {
    extern __shared__ char sm[];
    __nv_bfloat16* Ahi = (__nv_bfloat16*)sm;
    __nv_bfloat16* Alo = Ahi + 128 * ASTR;
    __nv_bfloat16* Bhi = Alo + 128 * ASTR;
    __nv_bfloat16* Blo = Bhi + 128 * ASTR;
    const uint32_t uAhi = s2u(Ahi), uAlo = s2u(Alo), uBhi = s2u(Bhi), uBlo = s2u(Blo);

    const int t = threadIdx.x;
    const int lane = t & 31, warp = t >> 5;
    const int bx = blockIdx.x, by = blockIdx.y;
    const int row0 = by * TM, col0 = bx * TN;
    const int warp_m = (warp >> 1) * 32;
    const int warp_n = (warp & 1) * 64;
    const int head = bx * 2 + (warp & 1);

    const __nv_bfloat16* wh = g_wthi + wsel * HD * HD;
    const __nv_bfloat16* wl = g_wtlo + wsel * HD * HD;

    float c[2][8][4];
#pragma unroll
    for (int i = 0; i < 2; i++)
#pragma unroll
        for (int j = 0; j < 8; j++)
#pragma unroll
            for (int q = 0; q < 4; q++) c[i][j][q] = 0.f;

    // ldmatrix address components
    const int a_row = ((lane >> 3) & 1) * 8 + (lane & 7);
    const int a_kof = (lane >> 4) * 8;
    const int b_nsel = (lane >> 4) & 1;
    const int b_ksel = (lane >> 3) & 1;
    const int b_row = (lane & 7);

    for (int ch = 0; ch < 4; ch++) {
        const int k0 = ch * KC;
        // ---- A: 128x64 fp32 -> BN + lrelu -> bf16 hi/lo ----
        {
            int r = t >> 1, c0i = (t & 1) * 32;
            int grow = row0 + r;
            float x[32];
            if (grow < MROWS) {
                const float4* p = (const float4*)&g_hout[(size_t)grow * HD + k0 + c0i];
#pragma unroll
                for (int q = 0; q < 8; q++) {
                    float4 v = p[q];
                    x[4 * q + 0] = v.x; x[4 * q + 1] = v.y; x[4 * q + 2] = v.z; x[4 * q + 3] = v.w;
                }
            } else {
#pragma unroll
                for (int j = 0; j < 32; j++) x[j] = 0.f;
            }
            const float4* scp = (const float4*)&g_scale[k0 + c0i];
            const float4* shp = (const float4*)&g_shift[k0 + c0i];
#pragma unroll
            for (int q = 0; q < 8; q++) {
                float4 sc = __ldg(&scp[q]);
                float4 sh = __ldg(&shp[q]);
                float v0 = fmaf(x[4 * q + 0], sc.x, sh.x);
                float v1 = fmaf(x[4 * q + 1], sc.y, sh.y);
                float v2 = fmaf(x[4 * q + 2], sc.z, sh.z);
                float v3 = fmaf(x[4 * q + 3], sc.w, sh.w);
                x[4 * q + 0] = v0 > 0.f ? v0 : 0.01f * v0;
                x[4 * q + 1] = v1 > 0.f ? v1 : 0.01f * v1;
                x[4 * q + 2] = v2 > 0.f ? v2 : 0.01f * v2;
                x[4 * q + 3] = v3 > 0.f ? v3 : 0.01f * v3;
            }
#pragma unroll
            for (int q = 0; q < 4; q++) {
                union { __nv_bfloat16 b[8]; uint4 u; } uh, ul;
#pragma unroll
                for (int j = 0; j < 8; j++) {
                    float xv = x[8 * q + j];
                    __nv_bfloat16 h = __float2bfloat16(xv);
                    uh.b[j] = h;
                    ul.b[j] = __float2bfloat16(xv - __bfloat162float(h));
                }
                *(uint4*)&Ahi[r * ASTR + c0i + 8 * q] = uh.u;
                *(uint4*)&Alo[r * ASTR + c0i + 8 * q] = ul.u;
            }
        }
        // ---- B: 128(n) x 64(k) bf16 hi/lo (precomputed) ----
        {
            int n = t >> 1, kh = (t & 1) * 32;
            int gn = col0 + n;                                  // FIX: column-block offset
            const uint4* ph = (const uint4*)&wh[gn * HD + k0 + kh];
            const uint4* pl = (const uint4*)&wl[gn * HD + k0 + kh];
#pragma unroll
            for (int q = 0; q < 4; q++) {
                *(uint4*)&Bhi[n * ASTR + kh + 8 * q] = __ldg(&ph[q]);
                *(uint4*)&Blo[n * ASTR + kh + 8 * q] = __ldg(&pl[q]);
            }
        }
        __syncthreads();

#pragma unroll
        for (int ks = 0; ks < 4; ks++) {
            uint32_t afh[2][4], afl[2][4];
            uint32_t bfh[8][2], bfl[8][2];
#pragma unroll
            for (int mt = 0; mt < 2; mt++) {
                uint32_t off = (uint32_t)(((warp_m + mt * 16 + a_row) * ASTR + 16 * ks + a_kof) * 2);
                ldsm4(afh[mt], uAhi + off);
                ldsm4(afl[mt], uAlo + off);
            }
#pragma unroll
            for (int p = 0; p < 4; p++) {
                uint32_t off = (uint32_t)(((warp_n + (2 * p + b_nsel) * 8 + b_row) * ASTR + 16 * ks + 8 * b_ksel) * 2);
                uint32_t r4[4];
                ldsm4(r4, uBhi + off);
                bfh[2 * p][0] = r4[0]; bfh[2 * p][1] = r4[1];
                bfh[2 * p + 1][0] = r4[2]; bfh[2 * p + 1][1] = r4[3];
                ldsm4(r4, uBlo + off);
                bfl[2 * p][0] = r4[0]; bfl[2 * p][1] = r4[1];
                bfl[2 * p + 1][0] = r4[2]; bfl[2 * p + 1][1] = r4[3];
            }
#pragma unroll
            for (int mt = 0; mt < 2; mt++)
#pragma unroll
                for (int nt = 0; nt < 8; nt++) {
                    mma16816(c[mt][nt], afh[mt], bfh[nt]);   // hi*hi
                    mma16816(c[mt][nt], afh[mt], bfl[nt]);   // hi*lo
                    mma16816(c[mt][nt], afl[mt], bfh[nt]);   // lo*hi
                }
        }
        __syncthreads();
    }

    // ---- epilogue: store D + fused el/er (warp covers exactly one head) ----
    float elacc[2][2] = {{0.f, 0.f}, {0.f, 0.f}};
    float eracc[2][2] = {{0.f, 0.f}, {0.f, 0.f}};
    const int qn = 2 * (lane & 3);
    const int g = lane >> 2;
#pragma unroll
    for (int mt = 0; mt < 2; mt++) {
#pragma unroll
        for (int nt = 0; nt < 8; nt++) {
            float v0 = c[mt][nt][0], v1 = c[mt][nt][1];
            float v2 = c[mt][nt][2], v3 = c[mt][nt][3];
            int cih = nt * 8 + qn;
            float a0 = __ldg(&al[head * DD + cih]), a1 = __ldg(&al[head * DD + cih + 1]);
            float r0 = __ldg(&ar[head * DD + cih]), r1 = __ldg(&ar[head * DD + cih + 1]);
            elacc[mt][0] = fmaf(v0, a0, fmaf(v1, a1, elacc[mt][0]));
            elacc[mt][1] = fmaf(v2, a0, fmaf(v3, a1, elacc[mt][1]));
            eracc[mt][0] = fmaf(v0, r0, fmaf(v1, r1, eracc[mt][0]));
            eracc[mt][1] = fmaf(v2, r0, fmaf(v3, r1, eracc[mt][1]));
            int gcol = col0 + warp_n + cih;
            int grow0 = row0 + warp_m + mt * 16 + g;
            int grow1 = grow0 + 8;
            if (grow0 < MROWS) *(float2*)&g_h[(size_t)grow0 * HD + gcol] = make_float2(v0, v1);
            if (grow1 < MROWS) *(float2*)&g_h[(size_t)grow1 * HD + gcol] = make_float2(v2, v3);
        }
    }
#pragma unroll
    for (int mt = 0; mt < 2; mt++)
#pragma unroll
        for (int half = 0; half < 2; half++) {
            float e = elacc[mt][half], r = eracc[mt][half];
            e += __shfl_xor_sync(0xffffffffu, e, 1);
            e += __shfl_xor_sync(0xffffffffu, e, 2);
            r += __shfl_xor_sync(0xffffffffu, r, 1);
            r += __shfl_xor_sync(0xffffffffu, r, 2);
            int row = row0 + warp_m + mt * 16 + half * 8 + g;
            if ((lane & 3) == 0 && row < MROWS) {
                g_el[row * HH + head] = e;
                g_er[row * HH + head] = r;
            }
        }
}

// ---------------- edge softmax + aggregation + fused BN partial stats ----------------
__global__ __launch_bounds__(256) void k_agg() {
    const int bn = blockIdx.x;
    const int b  = bn / NN;
    const int v  = bn - b * NN;
    const int t  = threadIdx.x;
    const int hh = t >> 6;
    const int d  = t & 63;

    const int e0 = g_rowstart[v];
    const int deg = g_rowstart[v + 1] - e0;
    float* outp = g_hout + (size_t)bn * HD;
    if (deg == 0) { outp[t] = 0.f; return; }

    __shared__ float sh_er[HH];
    __shared__ float sh_m[HH];
    __shared__ float sh_is[HH];
    __shared__ float sh_w[HH][32];
    __shared__ int   sh_src[32];

    if (t < HH) sh_er[t] = g_er[bn * HH + t];
    __syncthreads();

    const int w = t >> 5, lane = t & 31;
    if (w < HH) {
        float mv = -INFINITY;
        for (int i = lane; i < deg; i += 32) {
            int s = g_csr_src[e0 + i];
            float e = lk(g_el[(b * NN + s) * HH + w] + sh_er[w], 0.2f);
            mv = fmaxf(mv, e);
        }
#pragma unroll
        for (int off = 16; off; off >>= 1) mv = fmaxf(mv, __shfl_xor_sync(0xffffffffu, mv, off));
        if (lane == 0) sh_m[w] = mv;
    }
    __syncthreads();
    if (w < HH) {
        float sum = 0.f;
        float m = sh_m[w];
        for (int i = lane; i < deg; i += 32) {
            int s = g_csr_src[e0 + i];
            float e = lk(g_el[(b * NN + s) * HH + w] + sh_er[w], 0.2f);
            sum += __expf(e - m);
        }
#pragma unroll
        for (int off = 16; off; off >>= 1) sum += __shfl_xor_sync(0xffffffffu, sum, off);
        if (lane == 0) sh_is[w] = 1.f / sum;
    }
    __syncthreads();

    float a0 = 0.f, a1 = 0.f, a2 = 0.f, a3 = 0.f;
    for (int base = 0; base < deg; base += 32) {
        int len = min(32, deg - base);
        if (t < 128) {
            int i = t & 31, h2 = t >> 5;
            if (i < len) {
                int s = g_csr_src[e0 + base + i];
                if (t < 32) sh_src[i] = s;
                float e = lk(g_el[(b * NN + s) * HH + h2] + sh_er[h2], 0.2f);
                sh_w[h2][i] = __expf(e - sh_m[h2]) * sh_is[h2];
            }
        }
        __syncthreads();
        int i = 0;
        for (; i + 4 <= len; i += 4) {
            int s0 = sh_src[i], s1 = sh_src[i + 1], s2 = sh_src[i + 2], s3 = sh_src[i + 3];
            float w0 = sh_w[hh][i], w1 = sh_w[hh][i + 1], w2 = sh_w[hh][i + 2], w3 = sh_w[hh][i + 3];
            float v0 = g_h[(((size_t)b * NN + s0) << 8) + (hh << 6) + d];
            float v1 = g_h[(((size_t)b * NN + s1) << 8) + (hh << 6) + d];
            float v2 = g_h[(((size_t)b * NN + s2) << 8) + (hh << 6) + d];
            float v3 = g_h[(((size_t)b * NN + s3) << 8) + (hh << 6) + d];
            a0 = fmaf(w0, v0, a0);
            a1 = fmaf(w1, v1, a1);
            a2 = fmaf(w2, v2, a2);
            a3 = fmaf(w3, v3, a3);
        }
        for (; i < len; i++) {
            int s0 = sh_src[i];
            a0 = fmaf(sh_w[hh][i], g_h[(((size_t)b * NN + s0) << 8) + (hh << 6) + d], a0);
        }
        __syncthreads();
    }
    float acc = (a0 + a1) + (a2 + a3);
    outp[t] = acc;
    int slot = (bn & (NPART - 1)) * HD + t;
    atomicAdd(&g_part[slot], acc);
    atomicAdd(&g_partsq[slot], acc * acc);
}

// ---------------- BatchNorm finalize (reads partials, zeroes them for next layer) ----------------
__global__ void k_bnfin(const float* __restrict__ gamma, const float* __restrict__ beta) {
    int c = threadIdx.x;
    float s = 0.f, sq = 0.f;
#pragma unroll
    for (int i = 0; i < NPART; i++) {
        s  += g_part[i * HD + c];
        sq += g_partsq[i * HD + c];
        g_part[i * HD + c] = 0.f;
        g_partsq[i * HD + c] = 0.f;
    }
    float inv = 1.f / (float)MROWS;
    float mu = s * inv;
    float var = sq * inv - mu * mu;
    float sc = gamma[c] * rsqrtf(var + EPSBN);
    g_scale[c] = sc;
    g_shift[c] = beta[c] - mu * sc;
}

// ---------------- output projection (applies last BN) + autoregressive shift ----------------
__global__ void k_proj(const float* __restrict__ Wo, const float* __restrict__ bo,
                       float* __restrict__ out, int step) {
    int bn = blockIdx.x;
    int w = threadIdx.x >> 5, lane = threadIdx.x & 31;
    __shared__ float sval[OUTD];
    const float* hp = g_hout + (size_t)bn * HD;
    float sum = 0.f;
#pragma unroll
    for (int k = lane; k < HD; k += 32) {
        float xv = fmaf(hp[k], g_scale[k], g_shift[k]);
        xv = xv > 0.f ? xv : 0.01f * xv;
        sum = fmaf(xv, Wo[k * OUTD + w], sum);
    }
#pragma unroll
    for (int off = 16; off; off >>= 1) sum += __shfl_xor_sync(0xffffffffu, sum, off);
    if (lane == 0) sval[w] = sum + bo[w];

    float keep = 0.f;
    if (threadIdx.x < IND - OUTD) keep = g_x[bn * IND + threadIdx.x + OUTD];
    __syncthreads();
    if (threadIdx.x < IND - OUTD) g_x[bn * IND + threadIdx.x] = keep;
    else if (threadIdx.x < IND) g_x[bn * IND + threadIdx.x] = sval[threadIdx.x - (IND - OUTD)];
    if (threadIdx.x < OUTD) out[(bn * TSTEPS + step) * OUTD + threadIdx.x] = sval[threadIdx.x];
}

// ---------------- launcher ----------------
extern "C" void kernel_launch(void* const* d_in, const int* in_sizes, int n_in,
                              void* d_out, int out_size) {
    const float* xx  = (const float*)d_in[0];
    const int*   src = (const int*)d_in[1];
    const int*   dst = (const int*)d_in[2];
    const float *W[4], *al[4], *ar[4], *gamma[4], *beta[4];
    for (int l = 0; l < 4; l++) {
        W[l]     = (const float*)d_in[3 + 5 * l];
        al[l]    = (const float*)d_in[4 + 5 * l];
        ar[l]    = (const float*)d_in[5 + 5 * l];
        gamma[l] = (const float*)d_in[6 + 5 * l];
        beta[l]  = (const float*)d_in[7 + 5 * l];
    }
    const float* W_out = (const float*)d_in[23];
    const float* b_out = (const float*)d_in[24];
    float* out = (float*)d_out;

    cudaFuncSetAttribute(k_gemm, cudaFuncAttributeMaxDynamicSharedMemorySize, GSM_BYTES);

    k_copyx<<<(MROWS * IND + 255) / 256, 256>>>(xx);
    k_zero_counts<<<(NN + 255) / 256, 256>>>();
    k_count<<<(EE + 255) / 256, 256>>>(dst);
    k_scan<<<1, 1024>>>();
    k_fill<<<(EE + 255) / 256, 256>>>(src, dst);
    k_wprep<<<dim3(HD, 3), HD>>>(W[1], W[2], W[3]);

    dim3 ggrid(HD / TN, (MROWS + TM - 1) / TM);

    for (int step = 0; step < TSTEPS; step++) {
        for (int l = 0; l < 4; l++) {
            if (l == 0)
                k_fc0<<<MROWS, 256>>>(W[0], al[0], ar[0]);
            else
                k_gemm<<<ggrid, 256, GSM_BYTES>>>(l - 1, al[l], ar[l]);
            k_agg<<<MROWS, 256>>>();
            k_bnfin<<<1, HD>>>(gamma[l], beta[l]);
        }
        k_proj<<<MROWS, 96>>>(W_out, b_out, out, step);
    }
}